// round 2
// baseline (speedup 1.0000x reference)
#include <cuda_runtime.h>
#include <cuda_bf16.h>

// Problem constants (from reference): N=100000 nodes, E=1600000 edges, D=128, G=64
#define NN 100000
#define DD 128
#define GG 64

// Scratch (allocation-free rule: __device__ globals). ~154MB total.
__device__ __align__(16) float g_h0[NN * DD];
__device__ __align__(16) float g_h1[NN * DD];
__device__ __align__(16) float g_agg[NN * DD];
__device__ float g_cs[NN];   // holds deg_out, then rsqrt(deg_out)
__device__ float g_cd[NN];   // holds deg_in,  then rsqrt(deg_in)
__device__ __align__(16) float g_sums[GG * DD];
__device__ float g_cnt[GG];

// ---------------------------------------------------------------------------
// Degree / norm
// ---------------------------------------------------------------------------
__global__ void init_deg_kernel(int n) {
    int i = blockIdx.x * blockDim.x + threadIdx.x;
    if (i < n) { g_cs[i] = 1.0f; g_cd[i] = 1.0f; }  // self-loop contributes 1
}

__global__ void count_deg_kernel(const int* __restrict__ src,
                                 const int* __restrict__ dst, int e) {
    int i = blockIdx.x * blockDim.x + threadIdx.x;
    if (i < e) {
        atomicAdd(&g_cs[src[i]], 1.0f);
        atomicAdd(&g_cd[dst[i]], 1.0f);
    }
}

__global__ void finalize_norm_kernel(int n) {
    int i = blockIdx.x * blockDim.x + threadIdx.x;
    if (i < n) {
        g_cs[i] = rsqrtf(g_cs[i]);
        g_cd[i] = rsqrtf(g_cd[i]);
    }
}

// ---------------------------------------------------------------------------
// agg init with self-loop message: agg[i] = h[i] * cs[i]
// One thread per float4 (N*32 threads).
// ---------------------------------------------------------------------------
__global__ void init_agg_kernel(const float* __restrict__ h, int n) {
    int t = blockIdx.x * blockDim.x + threadIdx.x;
    if (t >= n * 32) return;
    int node = t >> 5;
    int q = t & 31;
    float c = g_cs[node];
    float4 v = ((const float4*)h)[(size_t)node * 32 + q];
    v.x *= c; v.y *= c; v.z *= c; v.w *= c;
    ((float4*)g_agg)[(size_t)node * 32 + q] = v;
}

// ---------------------------------------------------------------------------
// Edge scatter: agg[dst] += h[src] * cs[src].
// One warp per edge; each lane handles one float4 via vector red (no return).
// ---------------------------------------------------------------------------
__global__ void scatter_kernel(const float* __restrict__ h,
                               const int* __restrict__ src,
                               const int* __restrict__ dst, int e) {
    int w = (blockIdx.x * blockDim.x + threadIdx.x) >> 5;
    int lane = threadIdx.x & 31;
    if (w >= e) return;
    int s = src[w];
    int d = dst[w];
    float c = g_cs[s];
    float4 v = ((const float4*)h)[(size_t)s * 32 + lane];
    float* out = g_agg + (size_t)d * DD + lane * 4;
    asm volatile("red.global.add.v4.f32 [%0], {%1, %2, %3, %4};"
                 :: "l"(out), "f"(v.x * c), "f"(v.y * c), "f"(v.z * c), "f"(v.w * c)
                 : "memory");
}

// ---------------------------------------------------------------------------
// out = relu((agg * cd) @ W + b)
// Block: 256 threads, tile 64 rows x 128 cols. Each thread: 8 rows x 4 cols.
// W (128x128) fully in smem; A tile in smem with stride-129 padding.
// Within a warp all lanes share rx -> A reads are broadcast (conflict-free).
// ---------------------------------------------------------------------------
#define GEMM_SMEM ((128 * 128 + 64 * 129) * 4)

__global__ void __launch_bounds__(256, 2)
gemm_relu_kernel(const float* __restrict__ W, const float* __restrict__ b,
                 float* __restrict__ out, int n) {
    extern __shared__ float sh[];
    float* Wsh = sh;             // 128*128
    float* Ash = sh + 128 * 128; // 64*129 (padded)

    int t = threadIdx.x;
    int rows0 = blockIdx.x * 64;

    // Load W: 4096 float4s, 16 per thread
#pragma unroll
    for (int it = 0; it < 16; it++) {
        int e4 = t + it * 256;
        ((float4*)Wsh)[e4] = ((const float4*)W)[e4];
    }
    // Load A tile: 2048 float4s (64 rows x 32 quads), clamp OOB rows
#pragma unroll
    for (int it = 0; it < 8; it++) {
        int e4 = t + it * 256;
        int r = e4 >> 5;
        int kq = e4 & 31;
        int gr = rows0 + r;
        if (gr > n - 1) gr = n - 1;
        float4 v = ((const float4*)g_agg)[(size_t)gr * 32 + kq];
        float* dp = &Ash[r * 129 + kq * 4];
        dp[0] = v.x; dp[1] = v.y; dp[2] = v.z; dp[3] = v.w;
    }
    __syncthreads();

    int cx = t & 31;   // column group (4 cols)
    int rx = t >> 5;   // row sub-index within warp-row-group (0..7)

    float acc[8][4];
#pragma unroll
    for (int i = 0; i < 8; i++)
#pragma unroll
        for (int j = 0; j < 4; j++) acc[i][j] = 0.0f;

#pragma unroll 4
    for (int k = 0; k < 128; k++) {
        float4 w4 = *(const float4*)&Wsh[k * 128 + cx * 4];
#pragma unroll
        for (int i = 0; i < 8; i++) {
            float a = Ash[(rx + 8 * i) * 129 + k];
            acc[i][0] += a * w4.x;
            acc[i][1] += a * w4.y;
            acc[i][2] += a * w4.z;
            acc[i][3] += a * w4.w;
        }
    }

    float4 bb = ((const float4*)b)[cx];
#pragma unroll
    for (int i = 0; i < 8; i++) {
        int r = rows0 + rx + 8 * i;
        if (r < n) {
            float cdv = g_cd[r];
            float4 o;
            o.x = fmaxf(acc[i][0] * cdv + bb.x, 0.0f);
            o.y = fmaxf(acc[i][1] * cdv + bb.y, 0.0f);
            o.z = fmaxf(acc[i][2] * cdv + bb.z, 0.0f);
            o.w = fmaxf(acc[i][3] * cdv + bb.w, 0.0f);
            ((float4*)out)[(size_t)r * 32 + cx] = o;
        }
    }
}

// ---------------------------------------------------------------------------
// Mean pooling
// ---------------------------------------------------------------------------
__global__ void zero_pool_kernel() {
    int i = blockIdx.x * blockDim.x + threadIdx.x;
    if (i < GG * DD) g_sums[i] = 0.0f;
    if (i < GG) g_cnt[i] = 0.0f;
}

__global__ void pool_kernel(const float* __restrict__ h,
                            const int* __restrict__ gid, int n) {
    int w = (blockIdx.x * blockDim.x + threadIdx.x) >> 5;
    int lane = threadIdx.x & 31;
    if (w >= n) return;
    int g = gid[w];
    float4 v = ((const float4*)h)[(size_t)w * 32 + lane];
    float* out = g_sums + g * DD + lane * 4;
    asm volatile("red.global.add.v4.f32 [%0], {%1, %2, %3, %4};"
                 :: "l"(out), "f"(v.x), "f"(v.y), "f"(v.z), "f"(v.w)
                 : "memory");
    if (lane == 0) atomicAdd(&g_cnt[g], 1.0f);
}

__global__ void divide_kernel(float* __restrict__ out) {
    int i = blockIdx.x * blockDim.x + threadIdx.x;
    if (i < GG * DD) out[i] = g_sums[i] / fmaxf(g_cnt[i >> 7], 1.0f);
}

// ---------------------------------------------------------------------------
extern "C" void kernel_launch(void* const* d_in, const int* in_sizes, int n_in,
                              void* d_out, int out_size) {
    const float* x  = (const float*)d_in[0];
    const float* Ws[3] = {(const float*)d_in[1], (const float*)d_in[3], (const float*)d_in[5]};
    const float* bs[3] = {(const float*)d_in[2], (const float*)d_in[4], (const float*)d_in[6]};
    const int* src = (const int*)d_in[7];
    const int* dst = (const int*)d_in[8];
    const int* gid = (const int*)d_in[9];

    int n = in_sizes[0] / DD;   // 100000
    int e = in_sizes[7];        // 1600000

    cudaFuncSetAttribute(gemm_relu_kernel,
                         cudaFuncAttributeMaxDynamicSharedMemorySize, GEMM_SMEM);

    void* p0; cudaGetSymbolAddress(&p0, g_h0);
    void* p1; cudaGetSymbolAddress(&p1, g_h1);
    float* h0 = (float*)p0;
    float* h1 = (float*)p1;

    // degrees + norms
    init_deg_kernel<<<(n + 255) / 256, 256>>>(n);
    count_deg_kernel<<<(e + 255) / 256, 256>>>(src, dst, e);
    finalize_norm_kernel<<<(n + 255) / 256, 256>>>(n);

    const float* hin = x;
    float* houts[3] = {h0, h1, h0};
    for (int l = 0; l < 3; l++) {
        init_agg_kernel<<<(n * 32 + 255) / 256, 256>>>(hin, n);
        scatter_kernel<<<(int)(((size_t)e * 32 + 255) / 256), 256>>>(hin, src, dst, e);
        gemm_relu_kernel<<<(n + 63) / 64, 256, GEMM_SMEM>>>(Ws[l], bs[l], houts[l], n);
        hin = houts[l];
    }

    zero_pool_kernel<<<(GG * DD + 255) / 256, 256>>>();
    pool_kernel<<<(int)(((size_t)n * 32 + 255) / 256), 256>>>(hin, gid, n);
    divide_kernel<<<(GG * DD + 255) / 256, 256>>>((float*)d_out);
}

// round 3
// speedup vs baseline: 1.5659x; 1.5659x over previous
#include <cuda_runtime.h>
#include <cuda_bf16.h>

#define NN 100000
#define DD 128
#define GG 64
#define SCAN_B 256

// Scratch (__device__ globals; no allocation allowed)
__device__ __align__(16) float g_h0[NN * DD];
__device__ __align__(16) float g_h1[NN * DD];
__device__ __align__(16) float g_agg[NN * DD];
__device__ float g_cs[NN];
__device__ float g_cd[NN];
__device__ int   g_degout[NN];
__device__ int   g_degin[NN];
__device__ int   g_rowstart[NN];
__device__ int   g_cursor[NN];
__device__ int   g_csr[1700000];          // E max
__device__ int   g_blocksums[512];
__device__ int   g_blockoff[512];
__device__ __align__(16) float g_sums[GG * DD];
__device__ float g_cnt[GG];

// ---------------------------------------------------------------------------
// Degrees (int) + CSR build
// ---------------------------------------------------------------------------
__global__ void zero_int_kernel(int n) {
    int i = blockIdx.x * blockDim.x + threadIdx.x;
    if (i < n) { g_degout[i] = 0; g_degin[i] = 0; g_cursor[i] = 0; }
}

__global__ void count_deg_kernel(const int* __restrict__ src,
                                 const int* __restrict__ dst, int e) {
    int i = blockIdx.x * blockDim.x + threadIdx.x;
    if (i < e) {
        atomicAdd(&g_degout[src[i]], 1);
        atomicAdd(&g_degin[dst[i]], 1);
    }
}

__global__ void finalize_norm_kernel(int n) {
    int i = blockIdx.x * blockDim.x + threadIdx.x;
    if (i < n) {
        g_cs[i] = rsqrtf((float)(g_degout[i] + 1));  // +1 self-loop
        g_cd[i] = rsqrtf((float)(g_degin[i] + 1));
    }
}

// Block-level inclusive scan of degin -> per-block exclusive prefix + block sums
__global__ void scan1_kernel(int n) {
    __shared__ int s[SCAN_B];
    int t = threadIdx.x;
    int i = blockIdx.x * SCAN_B + t;
    int v = (i < n) ? g_degin[i] : 0;
    s[t] = v;
    __syncthreads();
#pragma unroll
    for (int off = 1; off < SCAN_B; off <<= 1) {
        int add = (t >= off) ? s[t - off] : 0;
        __syncthreads();
        s[t] += add;
        __syncthreads();
    }
    if (i < n) g_rowstart[i] = s[t] - v;       // exclusive within block
    if (t == SCAN_B - 1) g_blocksums[blockIdx.x] = s[t];
}

__global__ void scan2_kernel(int nb) {
    __shared__ int s[512];
    int t = threadIdx.x;
    int v = (t < nb) ? g_blocksums[t] : 0;
    s[t] = v;
    __syncthreads();
#pragma unroll
    for (int off = 1; off < 512; off <<= 1) {
        int add = (t >= off) ? s[t - off] : 0;
        __syncthreads();
        s[t] += add;
        __syncthreads();
    }
    if (t < nb) g_blockoff[t] = s[t] - v;      // exclusive
}

__global__ void scan3_kernel(int n) {
    int i = blockIdx.x * blockDim.x + threadIdx.x;
    if (i < n) g_rowstart[i] += g_blockoff[i >> 8];   // SCAN_B = 256
}

__global__ void fill_csr_kernel(const int* __restrict__ src,
                                const int* __restrict__ dst, int e) {
    int i = blockIdx.x * blockDim.x + threadIdx.x;
    if (i < e) {
        int d = dst[i];
        int pos = atomicAdd(&g_cursor[d], 1);
        g_csr[g_rowstart[d] + pos] = src[i];
    }
}

// ---------------------------------------------------------------------------
// Gather aggregation: agg[node] = cd[node] * ( h[node]*cs[node]
//                                + sum_{s in in-edges} h[s]*cs[s] )
// One warp per node; lane q handles float4 column q. No atomics.
// ---------------------------------------------------------------------------
__global__ void __launch_bounds__(256)
gather_kernel(const float* __restrict__ h, int n) {
    int w = (blockIdx.x * blockDim.x + threadIdx.x) >> 5;
    int lane = threadIdx.x & 31;
    if (w >= n) return;
    int node = w;
    int base = g_rowstart[node];
    int deg  = g_degin[node];

    float4 acc = __ldg((const float4*)h + (size_t)node * 32 + lane);
    float cself = g_cs[node];
    acc.x *= cself; acc.y *= cself; acc.z *= cself; acc.w *= cself;

    for (int j0 = 0; j0 < deg; j0 += 32) {
        int cnt = min(32, deg - j0);
        int sj = 0; float cj = 0.0f;
        if (lane < cnt) {
            sj = __ldg(&g_csr[base + j0 + lane]);
            cj = g_cs[sj];
        }
        int k = 0;
        for (; k + 4 <= cnt; k += 4) {
            int s0 = __shfl_sync(0xffffffffu, sj, k);
            int s1 = __shfl_sync(0xffffffffu, sj, k + 1);
            int s2 = __shfl_sync(0xffffffffu, sj, k + 2);
            int s3 = __shfl_sync(0xffffffffu, sj, k + 3);
            float c0 = __shfl_sync(0xffffffffu, cj, k);
            float c1 = __shfl_sync(0xffffffffu, cj, k + 1);
            float c2 = __shfl_sync(0xffffffffu, cj, k + 2);
            float c3 = __shfl_sync(0xffffffffu, cj, k + 3);
            float4 v0 = __ldg((const float4*)h + (size_t)s0 * 32 + lane);
            float4 v1 = __ldg((const float4*)h + (size_t)s1 * 32 + lane);
            float4 v2 = __ldg((const float4*)h + (size_t)s2 * 32 + lane);
            float4 v3 = __ldg((const float4*)h + (size_t)s3 * 32 + lane);
            acc.x += v0.x * c0; acc.y += v0.y * c0; acc.z += v0.z * c0; acc.w += v0.w * c0;
            acc.x += v1.x * c1; acc.y += v1.y * c1; acc.z += v1.z * c1; acc.w += v1.w * c1;
            acc.x += v2.x * c2; acc.y += v2.y * c2; acc.z += v2.z * c2; acc.w += v2.w * c2;
            acc.x += v3.x * c3; acc.y += v3.y * c3; acc.z += v3.z * c3; acc.w += v3.w * c3;
        }
        for (; k < cnt; k++) {
            int s0 = __shfl_sync(0xffffffffu, sj, k);
            float c0 = __shfl_sync(0xffffffffu, cj, k);
            float4 v0 = __ldg((const float4*)h + (size_t)s0 * 32 + lane);
            acc.x += v0.x * c0; acc.y += v0.y * c0; acc.z += v0.z * c0; acc.w += v0.w * c0;
        }
    }

    float cdv = g_cd[node];
    acc.x *= cdv; acc.y *= cdv; acc.z *= cdv; acc.w *= cdv;
    ((float4*)g_agg)[(size_t)node * 32 + lane] = acc;
}

// ---------------------------------------------------------------------------
// out = relu(agg @ W + b)    (agg is already fully normalized)
// ---------------------------------------------------------------------------
#define GEMM_SMEM ((128 * 128 + 64 * 129) * 4)

__global__ void __launch_bounds__(256, 2)
gemm_relu_kernel(const float* __restrict__ W, const float* __restrict__ b,
                 float* __restrict__ out, int n) {
    extern __shared__ float sh[];
    float* Wsh = sh;
    float* Ash = sh + 128 * 128;

    int t = threadIdx.x;
    int rows0 = blockIdx.x * 64;

#pragma unroll
    for (int it = 0; it < 16; it++) {
        int e4 = t + it * 256;
        ((float4*)Wsh)[e4] = ((const float4*)W)[e4];
    }
#pragma unroll
    for (int it = 0; it < 8; it++) {
        int e4 = t + it * 256;
        int r = e4 >> 5;
        int kq = e4 & 31;
        int gr = rows0 + r;
        if (gr > n - 1) gr = n - 1;
        float4 v = ((const float4*)g_agg)[(size_t)gr * 32 + kq];
        float* dp = &Ash[r * 129 + kq * 4];
        dp[0] = v.x; dp[1] = v.y; dp[2] = v.z; dp[3] = v.w;
    }
    __syncthreads();

    int cx = t & 31;
    int rx = t >> 5;

    float acc[8][4];
#pragma unroll
    for (int i = 0; i < 8; i++)
#pragma unroll
        for (int j = 0; j < 4; j++) acc[i][j] = 0.0f;

#pragma unroll 4
    for (int k = 0; k < 128; k++) {
        float4 w4 = *(const float4*)&Wsh[k * 128 + cx * 4];
#pragma unroll
        for (int i = 0; i < 8; i++) {
            float a = Ash[(rx + 8 * i) * 129 + k];
            acc[i][0] += a * w4.x;
            acc[i][1] += a * w4.y;
            acc[i][2] += a * w4.z;
            acc[i][3] += a * w4.w;
        }
    }

    float4 bb = ((const float4*)b)[cx];
#pragma unroll
    for (int i = 0; i < 8; i++) {
        int r = rows0 + rx + 8 * i;
        if (r < n) {
            float4 o;
            o.x = fmaxf(acc[i][0] + bb.x, 0.0f);
            o.y = fmaxf(acc[i][1] + bb.y, 0.0f);
            o.z = fmaxf(acc[i][2] + bb.z, 0.0f);
            o.w = fmaxf(acc[i][3] + bb.w, 0.0f);
            ((float4*)out)[(size_t)r * 32 + cx] = o;
        }
    }
}

// ---------------------------------------------------------------------------
// Mean pooling
// ---------------------------------------------------------------------------
__global__ void zero_pool_kernel() {
    int i = blockIdx.x * blockDim.x + threadIdx.x;
    if (i < GG * DD) g_sums[i] = 0.0f;
    if (i < GG) g_cnt[i] = 0.0f;
}

__global__ void pool_kernel(const float* __restrict__ h,
                            const int* __restrict__ gid, int n) {
    int w = (blockIdx.x * blockDim.x + threadIdx.x) >> 5;
    int lane = threadIdx.x & 31;
    if (w >= n) return;
    int g = gid[w];
    float4 v = ((const float4*)h)[(size_t)w * 32 + lane];
    float* out = g_sums + g * DD + lane * 4;
    asm volatile("red.global.add.v4.f32 [%0], {%1, %2, %3, %4};"
                 :: "l"(out), "f"(v.x), "f"(v.y), "f"(v.z), "f"(v.w)
                 : "memory");
    if (lane == 0) atomicAdd(&g_cnt[g], 1.0f);
}

__global__ void divide_kernel(float* __restrict__ out) {
    int i = blockIdx.x * blockDim.x + threadIdx.x;
    if (i < GG * DD) out[i] = g_sums[i] / fmaxf(g_cnt[i >> 7], 1.0f);
}

// ---------------------------------------------------------------------------
extern "C" void kernel_launch(void* const* d_in, const int* in_sizes, int n_in,
                              void* d_out, int out_size) {
    const float* x  = (const float*)d_in[0];
    const float* Ws[3] = {(const float*)d_in[1], (const float*)d_in[3], (const float*)d_in[5]};
    const float* bs[3] = {(const float*)d_in[2], (const float*)d_in[4], (const float*)d_in[6]};
    const int* src = (const int*)d_in[7];
    const int* dst = (const int*)d_in[8];
    const int* gid = (const int*)d_in[9];

    int n = in_sizes[0] / DD;          // 100000
    int e = in_sizes[7];               // 1600000
    int nb = (n + SCAN_B - 1) / SCAN_B;

    cudaFuncSetAttribute(gemm_relu_kernel,
                         cudaFuncAttributeMaxDynamicSharedMemorySize, GEMM_SMEM);

    void* p0; cudaGetSymbolAddress(&p0, g_h0);
    void* p1; cudaGetSymbolAddress(&p1, g_h1);
    float* h0 = (float*)p0;
    float* h1 = (float*)p1;

    // CSR build + norms
    zero_int_kernel<<<(n + 255) / 256, 256>>>(n);
    count_deg_kernel<<<(e + 255) / 256, 256>>>(src, dst, e);
    finalize_norm_kernel<<<(n + 255) / 256, 256>>>(n);
    scan1_kernel<<<nb, SCAN_B>>>(n);
    scan2_kernel<<<1, 512>>>(nb);
    scan3_kernel<<<(n + 255) / 256, 256>>>(n);
    fill_csr_kernel<<<(e + 255) / 256, 256>>>(src, dst, e);

    const float* hin = x;
    float* houts[3] = {h0, h1, h0};
    for (int l = 0; l < 3; l++) {
        gather_kernel<<<(int)(((size_t)n * 32 + 255) / 256), 256>>>(hin, n);
        gemm_relu_kernel<<<(n + 63) / 64, 256, GEMM_SMEM>>>(Ws[l], bs[l], houts[l], n);
        hin = houts[l];
    }

    zero_pool_kernel<<<(GG * DD + 255) / 256, 256>>>();
    pool_kernel<<<(int)(((size_t)n * 32 + 255) / 256), 256>>>(hin, gid, n);
    divide_kernel<<<(GG * DD + 255) / 256, 256>>>((float*)d_out);
}

// round 5
// speedup vs baseline: 2.0075x; 1.2820x over previous
#include <cuda_runtime.h>
#include <cuda_bf16.h>
#include <cstdint>

#define NN 100000
#define DD 128
#define GG 64
#define SCAN_B 256

// Scratch (__device__ globals; no allocation allowed)
__device__ __align__(16) float g_h0[NN * DD];
__device__ __align__(16) float g_h1[NN * DD];
__device__ __align__(16) float g_agg[NN * DD];
__device__ __align__(16) float g_wt[3 * DD * DD];   // W transposed + tf32-rounded: wt[n][k]
__device__ float g_cs[NN];
__device__ float g_cd[NN];
__device__ int   g_degout[NN];
__device__ int   g_degin[NN];
__device__ int   g_rowstart[NN];
__device__ int   g_cursor[NN];
__device__ int   g_csr[1700000];
__device__ int   g_blocksums[512];
__device__ int   g_blockoff[512];
__device__ __align__(16) float g_sums[GG * DD];
__device__ float g_cnt[GG];

__device__ __forceinline__ float to_tf32(float x) {
    float r;
    asm("cvt.rna.tf32.f32 %0, %1;" : "=f"(r) : "f"(x));
    return r;
}

// ---------------------------------------------------------------------------
// Degrees + CSR build
// ---------------------------------------------------------------------------
__global__ void zero_int_kernel(int n) {
    int i = blockIdx.x * blockDim.x + threadIdx.x;
    if (i < n) { g_degout[i] = 0; g_degin[i] = 0; g_cursor[i] = 0; }
}

__global__ void count_deg_kernel(const int* __restrict__ src,
                                 const int* __restrict__ dst, int e) {
    int i = blockIdx.x * blockDim.x + threadIdx.x;
    if (i < e) {
        atomicAdd(&g_degout[src[i]], 1);
        atomicAdd(&g_degin[dst[i]], 1);
    }
}

__global__ void finalize_norm_kernel(int n) {
    int i = blockIdx.x * blockDim.x + threadIdx.x;
    if (i < n) {
        g_cs[i] = rsqrtf((float)(g_degout[i] + 1));
        g_cd[i] = rsqrtf((float)(g_degin[i] + 1));
    }
}

__global__ void scan1_kernel(int n) {
    __shared__ int s[SCAN_B];
    int t = threadIdx.x;
    int i = blockIdx.x * SCAN_B + t;
    int v = (i < n) ? g_degin[i] : 0;
    s[t] = v;
    __syncthreads();
#pragma unroll
    for (int off = 1; off < SCAN_B; off <<= 1) {
        int add = (t >= off) ? s[t - off] : 0;
        __syncthreads();
        s[t] += add;
        __syncthreads();
    }
    if (i < n) g_rowstart[i] = s[t] - v;
    if (t == SCAN_B - 1) g_blocksums[blockIdx.x] = s[t];
}

__global__ void scan2_kernel(int nb) {
    __shared__ int s[512];
    int t = threadIdx.x;
    int v = (t < nb) ? g_blocksums[t] : 0;
    s[t] = v;
    __syncthreads();
#pragma unroll
    for (int off = 1; off < 512; off <<= 1) {
        int add = (t >= off) ? s[t - off] : 0;
        __syncthreads();
        s[t] += add;
        __syncthreads();
    }
    if (t < nb) g_blockoff[t] = s[t] - v;
}

__global__ void scan3_kernel(int n) {
    int i = blockIdx.x * blockDim.x + threadIdx.x;
    if (i < n) g_rowstart[i] += g_blockoff[i >> 8];
}

__global__ void fill_csr_kernel(const int* __restrict__ src,
                                const int* __restrict__ dst, int e) {
    int i = blockIdx.x * blockDim.x + threadIdx.x;
    if (i < e) {
        int d = dst[i];
        int pos = atomicAdd(&g_cursor[d], 1);
        g_csr[g_rowstart[d] + pos] = src[i];
    }
}

// ---------------------------------------------------------------------------
// W prep: wt[n][k] = tf32(W[k][n])
// ---------------------------------------------------------------------------
__global__ void prep_w_kernel(const float* __restrict__ W, float* __restrict__ wt) {
    int i = blockIdx.x * blockDim.x + threadIdx.x;   // 16384
    int k = i >> 7;
    int nn = i & 127;
    wt[nn * DD + k] = to_tf32(W[i]);
}

// ---------------------------------------------------------------------------
// Gather aggregation (unchanged from round 3)
// ---------------------------------------------------------------------------
__global__ void __launch_bounds__(256)
gather_kernel(const float* __restrict__ h, int n) {
    int w = (blockIdx.x * blockDim.x + threadIdx.x) >> 5;
    int lane = threadIdx.x & 31;
    if (w >= n) return;
    int node = w;
    int base = g_rowstart[node];
    int deg  = g_degin[node];

    float4 acc = __ldg((const float4*)h + (size_t)node * 32 + lane);
    float cself = g_cs[node];
    acc.x *= cself; acc.y *= cself; acc.z *= cself; acc.w *= cself;

    for (int j0 = 0; j0 < deg; j0 += 32) {
        int cnt = min(32, deg - j0);
        int sj = 0; float cj = 0.0f;
        if (lane < cnt) {
            sj = __ldg(&g_csr[base + j0 + lane]);
            cj = g_cs[sj];
        }
        int k = 0;
        for (; k + 4 <= cnt; k += 4) {
            int s0 = __shfl_sync(0xffffffffu, sj, k);
            int s1 = __shfl_sync(0xffffffffu, sj, k + 1);
            int s2 = __shfl_sync(0xffffffffu, sj, k + 2);
            int s3 = __shfl_sync(0xffffffffu, sj, k + 3);
            float c0 = __shfl_sync(0xffffffffu, cj, k);
            float c1 = __shfl_sync(0xffffffffu, cj, k + 1);
            float c2 = __shfl_sync(0xffffffffu, cj, k + 2);
            float c3 = __shfl_sync(0xffffffffu, cj, k + 3);
            float4 v0 = __ldg((const float4*)h + (size_t)s0 * 32 + lane);
            float4 v1 = __ldg((const float4*)h + (size_t)s1 * 32 + lane);
            float4 v2 = __ldg((const float4*)h + (size_t)s2 * 32 + lane);
            float4 v3 = __ldg((const float4*)h + (size_t)s3 * 32 + lane);
            acc.x += v0.x * c0; acc.y += v0.y * c0; acc.z += v0.z * c0; acc.w += v0.w * c0;
            acc.x += v1.x * c1; acc.y += v1.y * c1; acc.z += v1.z * c1; acc.w += v1.w * c1;
            acc.x += v2.x * c2; acc.y += v2.y * c2; acc.z += v2.z * c2; acc.w += v2.w * c2;
            acc.x += v3.x * c3; acc.y += v3.y * c3; acc.z += v3.z * c3; acc.w += v3.w * c3;
        }
        for (; k < cnt; k++) {
            int s0 = __shfl_sync(0xffffffffu, sj, k);
            float c0 = __shfl_sync(0xffffffffu, cj, k);
            float4 v0 = __ldg((const float4*)h + (size_t)s0 * 32 + lane);
            acc.x += v0.x * c0; acc.y += v0.y * c0; acc.z += v0.z * c0; acc.w += v0.w * c0;
        }
    }

    float cdv = g_cd[node];
    acc.x *= cdv; acc.y *= cdv; acc.z *= cdv; acc.w *= cdv;
    ((float4*)g_agg)[(size_t)node * 32 + lane] = acc;
}

// ---------------------------------------------------------------------------
// Tensor-core GEMM via portable mma.sync tf32 (m16n8k8).
// out = relu(agg @ W + b). One CTA per 128 rows; 8 warps, each 32(M)x64(N).
// A and Wt staged in smem with stride 132 (conflict-free fragment loads).
// ---------------------------------------------------------------------------
#define GSTR 132
#define GT_SMEM (2 * 128 * GSTR * 4)

__global__ void __launch_bounds__(256, 1)
gemm_mma_kernel(const float* __restrict__ wt, const float* __restrict__ b,
                float* __restrict__ out, int n) {
    extern __shared__ float sh[];
    float* Bsm = sh;               // 128 x GSTR : Wt[n][k]
    float* Asm = sh + 128 * GSTR;  // 128 x GSTR : A[m][k] (tf32-rounded)

    int t = threadIdx.x;
    int rows0 = blockIdx.x * 128;

    // Stage Wt (already tf32)
#pragma unroll
    for (int it = 0; it < 16; it++) {
        int e4 = t + it * 256;
        int r = e4 >> 5, kq = e4 & 31;
        float4 v = __ldg((const float4*)wt + e4);
        *(float4*)&Bsm[r * GSTR + kq * 4] = v;
    }
    // Stage A tile (round to tf32)
#pragma unroll
    for (int it = 0; it < 16; it++) {
        int e4 = t + it * 256;
        int r = e4 >> 5, kq = e4 & 31;
        int gr = rows0 + r;
        if (gr > n - 1) gr = n - 1;
        float4 v = __ldg((const float4*)g_agg + (size_t)gr * 32 + kq);
        v.x = to_tf32(v.x); v.y = to_tf32(v.y); v.z = to_tf32(v.z); v.w = to_tf32(v.w);
        *(float4*)&Asm[r * GSTR + kq * 4] = v;
    }
    __syncthreads();

    int wid = t >> 5, lane = t & 31;
    int groupID = lane >> 2, ktid = lane & 3;
    int warpM = (wid & 3) * 32;
    int warpN = (wid >> 2) * 64;

    float acc[2][8][4];
#pragma unroll
    for (int mt = 0; mt < 2; mt++)
#pragma unroll
        for (int nt = 0; nt < 8; nt++)
#pragma unroll
            for (int q = 0; q < 4; q++) acc[mt][nt][q] = 0.0f;

#pragma unroll
    for (int k0 = 0; k0 < 128; k0 += 8) {
        uint32_t a[2][4];
#pragma unroll
        for (int mt = 0; mt < 2; mt++) {
            int r0 = warpM + mt * 16 + groupID;
            a[mt][0] = __float_as_uint(Asm[r0 * GSTR + k0 + ktid]);
            a[mt][1] = __float_as_uint(Asm[(r0 + 8) * GSTR + k0 + ktid]);
            a[mt][2] = __float_as_uint(Asm[r0 * GSTR + k0 + ktid + 4]);
            a[mt][3] = __float_as_uint(Asm[(r0 + 8) * GSTR + k0 + ktid + 4]);
        }
#pragma unroll
        for (int nt = 0; nt < 8; nt++) {
            int c0 = warpN + nt * 8 + groupID;
            uint32_t b0 = __float_as_uint(Bsm[c0 * GSTR + k0 + ktid]);
            uint32_t b1 = __float_as_uint(Bsm[c0 * GSTR + k0 + ktid + 4]);
#pragma unroll
            for (int mt = 0; mt < 2; mt++) {
                asm volatile(
                    "mma.sync.aligned.m16n8k8.row.col.f32.tf32.tf32.f32 "
                    "{%0,%1,%2,%3}, {%4,%5,%6,%7}, {%8,%9}, {%0,%1,%2,%3};"
                    : "+f"(acc[mt][nt][0]), "+f"(acc[mt][nt][1]),
                      "+f"(acc[mt][nt][2]), "+f"(acc[mt][nt][3])
                    : "r"(a[mt][0]), "r"(a[mt][1]), "r"(a[mt][2]), "r"(a[mt][3]),
                      "r"(b0), "r"(b1));
            }
        }
    }

    // Epilogue: bias + relu, float2 stores
#pragma unroll
    for (int mt = 0; mt < 2; mt++) {
        int r0 = rows0 + warpM + mt * 16 + groupID;
        int r1 = r0 + 8;
#pragma unroll
        for (int nt = 0; nt < 8; nt++) {
            int col = warpN + nt * 8 + 2 * ktid;
            float2 bb = __ldg((const float2*)(b + col));
            if (r0 < n) {
                float2 o;
                o.x = fmaxf(acc[mt][nt][0] + bb.x, 0.0f);
                o.y = fmaxf(acc[mt][nt][1] + bb.y, 0.0f);
                *(float2*)(out + (size_t)r0 * DD + col) = o;
            }
            if (r1 < n) {
                float2 o;
                o.x = fmaxf(acc[mt][nt][2] + bb.x, 0.0f);
                o.y = fmaxf(acc[mt][nt][3] + bb.y, 0.0f);
                *(float2*)(out + (size_t)r1 * DD + col) = o;
            }
        }
    }
}

// ---------------------------------------------------------------------------
// Mean pooling
// ---------------------------------------------------------------------------
__global__ void zero_pool_kernel() {
    int i = blockIdx.x * blockDim.x + threadIdx.x;
    if (i < GG * DD) g_sums[i] = 0.0f;
    if (i < GG) g_cnt[i] = 0.0f;
}

__global__ void pool_kernel(const float* __restrict__ h,
                            const int* __restrict__ gid, int n) {
    int w = (blockIdx.x * blockDim.x + threadIdx.x) >> 5;
    int lane = threadIdx.x & 31;
    if (w >= n) return;
    int g = gid[w];
    float4 v = ((const float4*)h)[(size_t)w * 32 + lane];
    float* out = g_sums + g * DD + lane * 4;
    asm volatile("red.global.add.v4.f32 [%0], {%1, %2, %3, %4};"
                 :: "l"(out), "f"(v.x), "f"(v.y), "f"(v.z), "f"(v.w)
                 : "memory");
    if (lane == 0) atomicAdd(&g_cnt[g], 1.0f);
}

__global__ void divide_kernel(float* __restrict__ out) {
    int i = blockIdx.x * blockDim.x + threadIdx.x;
    if (i < GG * DD) out[i] = g_sums[i] / fmaxf(g_cnt[i >> 7], 1.0f);
}

// ---------------------------------------------------------------------------
extern "C" void kernel_launch(void* const* d_in, const int* in_sizes, int n_in,
                              void* d_out, int out_size) {
    const float* x  = (const float*)d_in[0];
    const float* Ws[3] = {(const float*)d_in[1], (const float*)d_in[3], (const float*)d_in[5]};
    const float* bs[3] = {(const float*)d_in[2], (const float*)d_in[4], (const float*)d_in[6]};
    const int* src = (const int*)d_in[7];
    const int* dst = (const int*)d_in[8];
    const int* gid = (const int*)d_in[9];

    int n = in_sizes[0] / DD;          // 100000
    int e = in_sizes[7];               // 1600000
    int nb = (n + SCAN_B - 1) / SCAN_B;

    cudaFuncSetAttribute(gemm_mma_kernel,
                         cudaFuncAttributeMaxDynamicSharedMemorySize, GT_SMEM);

    void* p0; cudaGetSymbolAddress(&p0, g_h0);
    void* p1; cudaGetSymbolAddress(&p1, g_h1);
    void* pw; cudaGetSymbolAddress(&pw, g_wt);
    float* h0 = (float*)p0;
    float* h1 = (float*)p1;
    float* wt = (float*)pw;

    // W prep (independent; do first)
    for (int l = 0; l < 3; l++)
        prep_w_kernel<<<64, 256>>>(Ws[l], wt + l * DD * DD);

    // CSR build + norms
    zero_int_kernel<<<(n + 255) / 256, 256>>>(n);
    count_deg_kernel<<<(e + 255) / 256, 256>>>(src, dst, e);
    finalize_norm_kernel<<<(n + 255) / 256, 256>>>(n);
    scan1_kernel<<<nb, SCAN_B>>>(n);
    scan2_kernel<<<1, 512>>>(nb);
    scan3_kernel<<<(n + 255) / 256, 256>>>(n);
    fill_csr_kernel<<<(e + 255) / 256, 256>>>(src, dst, e);

    const float* hin = x;
    float* houts[3] = {h0, h1, h0};
    int gtiles = (n + 127) / 128;
    for (int l = 0; l < 3; l++) {
        gather_kernel<<<(int)(((size_t)n * 32 + 255) / 256), 256>>>(hin, n);
        gemm_mma_kernel<<<gtiles, 256, GT_SMEM>>>(wt + l * DD * DD, bs[l], houts[l], n);
        hin = houts[l];
    }

    zero_pool_kernel<<<(GG * DD + 255) / 256, 256>>>();
    pool_kernel<<<(int)(((size_t)n * 32 + 255) / 256), 256>>>(hin, gid, n);
    divide_kernel<<<(GG * DD + 255) / 256, 256>>>((float*)d_out);
}